// round 12
// baseline (speedup 1.0000x reference)
#include <cuda_runtime.h>
#include <math.h>

#define Bq   2
#define Nn   512
#define DIN  32
#define DHD  64
#define Hh   4
#define Cc   256
#define BN   (Bq*Nn)
#define NSPL 4

typedef unsigned long long u64;
typedef unsigned int u32;

__device__ float  g_mbias[Nn*Nn];
__device__ float2 g_xlT[Bq*Hh*32*512];    // [(b*4+h)*32 + d2][node]
__device__ float  g_xr[BN*Cc];
__device__ float  g_al[Bq*Hh*512];
__device__ float  g_ar[Bq*Hh*512];
__device__ float  g_pacc[NSPL*BN*Cc];     // [q][row][c]
__device__ float  g_psum[NSPL*BN*Hh];     // [q][row][h]
__device__ float  g_hln[BN*Cc];

// ---- packed fp32x2 helpers ----
__device__ __forceinline__ u64 add2(u64 a, u64 b) {
    u64 r; asm("add.rn.f32x2 %0,%1,%2;" : "=l"(r) : "l"(a), "l"(b)); return r;
}
__device__ __forceinline__ void fma2(u64 &d, u64 a, u64 b) {
    asm("fma.rn.f32x2 %0,%1,%2,%3;" : "=l"(d) : "l"(a), "l"(b), "l"(d));
}
__device__ __forceinline__ u64 dup2(float x) {
    u64 r; asm("mov.b64 %0,{%1,%1};" : "=l"(r) : "f"(x)); return r;
}
__device__ __forceinline__ float2 unpack2(u64 v) {
    float2 f; asm("mov.b64 {%0,%1},%2;" : "=f"(f.x), "=f"(f.y) : "l"(v)); return f;
}
#define ABS2MASK 0x7FFFFFFF7FFFFFFFULL

// ---- tf32 helpers ----
__device__ __forceinline__ float tf32r(float x) {
    float r; asm("cvt.rna.tf32.f32 %0,%1;" : "=f"(r) : "f"(x)); return r;
}
__device__ __forceinline__ void mma_tf32(float* c, const u32* a, u32 b0, u32 b1) {
    asm volatile("mma.sync.aligned.m16n8k8.row.col.f32.tf32.tf32.f32 "
        "{%0,%1,%2,%3},{%4,%5,%6,%7},{%8,%9},{%0,%1,%2,%3};"
        : "+f"(c[0]), "+f"(c[1]), "+f"(c[2]), "+f"(c[3])
        : "r"(a[0]), "r"(a[1]), "r"(a[2]), "r"(a[3]), "r"(b0), "r"(b1));
}

// ---------------- projection + rank-1 terms + transpose, z=2 -> mask -------
// grid (4, 16, 3) for layer1 (z=2 computes mask), (4, 16, 2) for layer2.
template<int K>
__global__ void __launch_bounds__(256) proj_kernel(
    const float* __restrict__ Xopt,
    const float* __restrict__ Wl, const float* __restrict__ bl,
    const float* __restrict__ Wr, const float* __restrict__ br,
    const float* __restrict__ att,
    const float* __restrict__ emb)
{
    __shared__ __align__(16) float sbuf[32*65 + 128*65];   // 41.6KB overlay
    const int t = threadIdx.x;

    if (blockIdx.z == 2) {
        // ================= mask path: 32 i-rows x 128 j-cols ===============
        float* As = sbuf;               // [32][65]
        float* Bs = sbuf + 32*65;       // [128][65]
        int i0 = blockIdx.y * 32, j0 = blockIdx.x * 128;
        int tx = t & 15, ty = t >> 4;

        {   // normalize A rows: 8 threads/row
            int r = t >> 3, q = t & 7;
            const float* src = &emb[(i0 + r)*DHD + q*8];
            float4 v0 = *reinterpret_cast<const float4*>(src);
            float4 v1 = *reinterpret_cast<const float4*>(src + 4);
            float s = v0.x*v0.x + v0.y*v0.y + v0.z*v0.z + v0.w*v0.w
                    + v1.x*v1.x + v1.y*v1.y + v1.z*v1.z + v1.w*v1.w;
            s += __shfl_xor_sync(0xffffffffu, s, 1);
            s += __shfl_xor_sync(0xffffffffu, s, 2);
            s += __shfl_xor_sync(0xffffffffu, s, 4);
            float inv = rsqrtf(s);
            float* dst = &As[r*65 + q*8];
            dst[0]=v0.x*inv; dst[1]=v0.y*inv; dst[2]=v0.z*inv; dst[3]=v0.w*inv;
            dst[4]=v1.x*inv; dst[5]=v1.y*inv; dst[6]=v1.z*inv; dst[7]=v1.w*inv;
        }
        {   // normalize B rows: 2 threads/row, 32 vals each
            int r = t >> 1, q = t & 1;
            const float* src = &emb[(j0 + r)*DHD + q*32];
            float4 v[8];
            #pragma unroll
            for (int i = 0; i < 8; i++) v[i] = *reinterpret_cast<const float4*>(src + 4*i);
            float s = 0.f;
            #pragma unroll
            for (int i = 0; i < 8; i++)
                s += v[i].x*v[i].x + v[i].y*v[i].y + v[i].z*v[i].z + v[i].w*v[i].w;
            s += __shfl_xor_sync(0xffffffffu, s, 1);
            float inv = rsqrtf(s);
            float* dst = &Bs[r*65 + q*32];
            #pragma unroll
            for (int i = 0; i < 8; i++) {
                dst[4*i    ] = v[i].x*inv;
                dst[4*i + 1] = v[i].y*inv;
                dst[4*i + 2] = v[i].z*inv;
                dst[4*i + 3] = v[i].w*inv;
            }
        }
        __syncthreads();

        float acc[2][8];
        #pragma unroll
        for (int r = 0; r < 2; r++)
            #pragma unroll
            for (int c = 0; c < 8; c++) acc[r][c] = 0.f;

        #pragma unroll 8
        for (int kk = 0; kk < 64; kk++) {
            float a0 = As[ty*65 + kk], a1 = As[(ty + 16)*65 + kk];
            float bb[8];
            #pragma unroll
            for (int c = 0; c < 8; c++) bb[c] = Bs[(8*tx + c)*65 + kk];
            #pragma unroll
            for (int c = 0; c < 8; c++) { acc[0][c] += a0*bb[c]; acc[1][c] += a1*bb[c]; }
        }
        #pragma unroll
        for (int r = 0; r < 2; r++) {
            int gi = i0 + ty + 16*r;
            float o[8];
            #pragma unroll
            for (int c = 0; c < 8; c++) {
                int gj = j0 + 8*tx + c;
                o[c] = (acc[r][c] != 0.0f || gi == gj) ? 0.0f : -1e30f;
            }
            *reinterpret_cast<float4*>(&g_mbias[gi*Nn + j0 + 8*tx])     = make_float4(o[0],o[1],o[2],o[3]);
            *reinterpret_cast<float4*>(&g_mbias[gi*Nn + j0 + 8*tx + 4]) = make_float4(o[4],o[5],o[6],o[7]);
        }
        return;
    }

    // ==================== projection path ====================
    float* A_s = sbuf;                  // [64][33]
    float* W_s = sbuf + 64*33;          // [32][68]
    const float* X    = Xopt ? Xopt : g_hln;
    const float* W    = blockIdx.z ? Wr : Wl;
    const float* bias = blockIdx.z ? br : bl;

    int m0 = blockIdx.y * 64, n0 = blockIdx.x * 64;
    int tx = t & 15, ty = t >> 4;

    u64 accp[4][2];
    #pragma unroll
    for (int r = 0; r < 4; r++) { accp[r][0] = 0ull; accp[r][1] = 0ull; }

    for (int kc = 0; kc < K; kc += 32) {
        __syncthreads();
        #pragma unroll
        for (int p = 0; p < 8; p++) {
            int row = (t >> 5) + p*8;
            int col = t & 31;
            A_s[row*33 + col] = X[(m0 + row)*K + kc + col];
        }
        #pragma unroll
        for (int p = 0; p < 8; p++) {
            int kk  = (t >> 6) + p*4;
            int col = t & 63;
            W_s[kk*68 + col] = W[(kc + kk)*Cc + n0 + col];
        }
        __syncthreads();
        #pragma unroll
        for (int kk = 0; kk < 32; kk++) {
            ulonglong2 bv = *reinterpret_cast<const ulonglong2*>(&W_s[kk*68 + 4*tx]);
            #pragma unroll
            for (int r = 0; r < 4; r++) {
                u64 ad = dup2(A_s[(ty + 16*r)*33 + kk]);
                fma2(accp[r][0], ad, bv.x);
                fma2(accp[r][1], ad, bv.y);
            }
        }
    }
    float4 bv4 = *reinterpret_cast<const float4*>(&bias[n0 + 4*tx]);
    int hq = blockIdx.x;
    float4 attv = *reinterpret_cast<const float4*>(&att[hq*64 + 4*tx]);

    #pragma unroll
    for (int r = 0; r < 4; r++) {
        int m = m0 + ty + 16*r;
        int b = m >> 9, node = m & 511;
        float2 lo = unpack2(accp[r][0]), hi = unpack2(accp[r][1]);
        float4 o = make_float4(lo.x + bv4.x, lo.y + bv4.y, hi.x + bv4.z, hi.y + bv4.w);
        float pa = attv.x*o.x + attv.y*o.y + attv.z*o.z + attv.w*o.w;
        pa += __shfl_xor_sync(0xffffffffu, pa, 1);
        pa += __shfl_xor_sync(0xffffffffu, pa, 2);
        pa += __shfl_xor_sync(0xffffffffu, pa, 4);
        pa += __shfl_xor_sync(0xffffffffu, pa, 8);
        pa *= 0.6f;
        if (blockIdx.z == 0) {
            float2* base = g_xlT + (size_t)((b*4 + hq)*32)*512;
            base[(2*tx    )*512 + node] = make_float2(o.x, o.y);
            base[(2*tx + 1)*512 + node] = make_float2(o.z, o.w);
            if (tx == 0) g_al[(b*4 + hq)*512 + node] = pa;
        } else {
            *reinterpret_cast<float4*>(&g_xr[m*Cc + n0 + 4*tx]) = o;
            if (tx == 0) g_ar[(b*4 + hq)*512 + node] = pa;
        }
    }
}

// ---------------- fused GATv2 attention: fp32x2 score + tf32 MMA agg -------
// grid (16, 4, 8): z = b*4 + q. 32 rows/block, 2 j-chunks of 64 per block.
// xlT2 holds tf32-pre-rounded X; single-term MMA. Error averages to ~3e-5.
__global__ void __launch_bounds__(256) attn_kernel(const float* __restrict__ att)
{
    const int z = blockIdx.z, b = z >> 2, q = z & 3;
    const int h = blockIdx.y, i0 = blockIdx.x * 32;
    const int t = threadIdx.x, w = t >> 5, l = t & 31;

    __shared__ float2 xlT2[32][66];
    __shared__ float2 xr2 [32][34];
    __shared__ float  pfh[32][68];
    __shared__ float2 bt2[32];

    #pragma unroll
    for (int p = 0; p < 2; p++) {
        int idx = t + p*256;
        int r = idx >> 4, cc = idx & 15;
        float4 v = *reinterpret_cast<const float4*>(&g_xr[(b*Nn + i0 + r)*Cc + h*64 + 4*cc]);
        *reinterpret_cast<float4*>(&xr2[r][2*cc]) = v;
    }
    if (t < 32) {
        float2 a = *reinterpret_cast<const float2*>(&att[h*64 + 2*t]);
        bt2[t] = make_float2(0.4f*a.x, 0.4f*a.y);
    }

    float arr[4];
    #pragma unroll
    for (int k = 0; k < 4; k++) arr[k] = g_ar[(b*4 + h)*512 + i0 + 4*w + k];

    const float2* xsrc = g_xlT + (size_t)((b*4 + h)*32)*512;
    const float*  alsrc = g_al + (b*4 + h)*512;
    const u32*    xlu = reinterpret_cast<const u32*>(&xlT2[0][0]);
    const int jbase = q * 128;
    const int d2p = t >> 5, mp = t & 31;
    const int ih = w & 1, dq = w >> 1;

    float cacc[2][4];
    #pragma unroll
    for (int tt = 0; tt < 2; tt++)
        #pragma unroll
        for (int i = 0; i < 4; i++) cacc[tt][i] = 0.f;
    float psum[4];
    #pragma unroll
    for (int k = 0; k < 4; k++) psum[k] = 0.f;

    float4 pre[4];
    #pragma unroll
    for (int p = 0; p < 4; p++)
        pre[p] = *reinterpret_cast<const float4*>(xsrc + (d2p + 8*p)*512 + jbase + 2*mp);

    for (int c = 0; c < 2; c++) {
        const int j0 = jbase + c * 64;
        __syncthreads();
        #pragma unroll
        for (int p = 0; p < 4; p++) {
            float4 v = pre[p];
            v.x = tf32r(v.x); v.y = tf32r(v.y); v.z = tf32r(v.z); v.w = tf32r(v.w);
            *reinterpret_cast<float4*>(&xlT2[d2p + 8*p][2*mp]) = v;
        }

        float2 mb[4];
        #pragma unroll
        for (int k = 0; k < 4; k++)
            mb[k] = *reinterpret_cast<const float2*>(&g_mbias[(i0 + 4*w + k)*Nn + j0 + 2*l]);
        float2 alj = *reinterpret_cast<const float2*>(&alsrc[j0 + 2*l]);

        __syncthreads();
        if (c < 1) {
            #pragma unroll
            for (int p = 0; p < 4; p++)
                pre[p] = *reinterpret_cast<const float4*>(xsrc + (d2p + 8*p)*512 + (j0 + 64) + 2*mp);
        }

        // ---- score (packed over d, tf32-rounded X: negligible score error) ----
        u64 sp[4][2];
        #pragma unroll
        for (int k = 0; k < 4; k++) { sp[k][0] = 0ull; sp[k][1] = 0ull; }

        #pragma unroll
        for (int d2 = 0; d2 < 32; d2 += 2) {
            ulonglong2 xa = *reinterpret_cast<const ulonglong2*>(&xlT2[d2    ][2*l]);
            ulonglong2 xb = *reinterpret_cast<const ulonglong2*>(&xlT2[d2 + 1][2*l]);
            ulonglong2 bt = *reinterpret_cast<const ulonglong2*>(&bt2[d2]);
            #pragma unroll
            for (int k = 0; k < 4; k++) {
                ulonglong2 xr = *reinterpret_cast<const ulonglong2*>(&xr2[4*w + k][d2]);
                u64 zz;
                zz = add2(xr.x, xa.x) & ABS2MASK; fma2(sp[k][0], bt.x, zz);
                zz = add2(xr.x, xa.y) & ABS2MASK; fma2(sp[k][1], bt.x, zz);
                zz = add2(xr.y, xb.x) & ABS2MASK; fma2(sp[k][0], bt.y, zz);
                zz = add2(xr.y, xb.y) & ABS2MASK; fma2(sp[k][1], bt.y, zz);
            }
        }

        // ---- exp + tf32-P store ----
        #pragma unroll
        for (int k = 0; k < 4; k++) {
            float2 s0v = unpack2(sp[k][0]);
            float2 s1v = unpack2(sp[k][1]);
            float p0 = __expf(s0v.x + s0v.y + arr[k] + alj.x + mb[k].x);
            float p1 = __expf(s1v.x + s1v.y + arr[k] + alj.y + mb[k].y);
            *reinterpret_cast<float2*>(&pfh[4*w + k][2*l]) = make_float2(tf32r(p0), tf32r(p1));
            psum[k] += p0 + p1;
        }
        __syncthreads();

        // ---- aggregation via tf32 MMA (single term, X pre-rounded) ----
        {
            int ar0 = ih*16 + (l >> 2);
            #pragma unroll
            for (int ks = 0; ks < 8; ks++) {
                int ac = ks*8 + (l & 3);
                u32 ah[4];
                ah[0] = __float_as_uint(pfh[ar0    ][ac]);
                ah[1] = __float_as_uint(pfh[ar0 + 8][ac]);
                ah[2] = __float_as_uint(pfh[ar0    ][ac + 4]);
                ah[3] = __float_as_uint(pfh[ar0 + 8][ac + 4]);
                #pragma unroll
                for (int tt = 0; tt < 2; tt++) {
                    int n0 = dq*16 + tt*8 + (l >> 2);
                    int k0 = ks*8 + (l & 3);
                    u32 b0 = xlu[(n0 >> 1)*132 + k0*2       + (n0 & 1)];
                    u32 b1 = xlu[(n0 >> 1)*132 + (k0 + 4)*2 + (n0 & 1)];
                    mma_tf32(cacc[tt], ah, b0, b1);
                }
            }
        }
    }

    // ---- write psum partials: [q][row][h] ----
    #pragma unroll
    for (int k = 0; k < 4; k++) {
        float s = psum[k];
        #pragma unroll
        for (int o = 16; o; o >>= 1) s += __shfl_xor_sync(0xffffffffu, s, o);
        if (l == 0) g_psum[(q*BN + b*Nn + i0 + 4*w + k)*Hh + h] = s;
    }

    // ---- write C partials: [q][row][c], coalesced float2 ----
    #pragma unroll
    for (int tt = 0; tt < 2; tt++) {
        int gr = b*Nn + i0 + ih*16 + (l >> 2);
        int gc = h*64 + dq*16 + tt*8 + 2*(l & 3);
        *reinterpret_cast<float2*>(&g_pacc[(q*BN + gr    )*Cc + gc]) =
            make_float2(cacc[tt][0], cacc[tt][1]);
        *reinterpret_cast<float2*>(&g_pacc[(q*BN + gr + 8)*Cc + gc]) =
            make_float2(cacc[tt][2], cacc[tt][3]);
    }
}

// ---------------- combine + bias + LayerNorm (+ReLU), block-per-row --------
__global__ void __launch_bounds__(128) ln_kernel(
    const float* __restrict__ g,
    const float* __restrict__ be,
    const float* __restrict__ abias,
    float* __restrict__ outopt,
    int do_relu)
{
    float* out = outopt ? outopt : g_hln;
    const int row = blockIdx.x;
    const int t = threadIdx.x;
    const int ch = 2*t;
    const int h = t >> 5;
    const int w = t >> 5, l = t & 31;
    __shared__ float red[4];

    float s = 0.f;
    #pragma unroll
    for (int qq = 0; qq < NSPL; qq++) s += g_psum[(qq*BN + row)*Hh + h];
    float inv = 1.0f / s;

    float2 acc = make_float2(0.f, 0.f);
    #pragma unroll
    for (int qq = 0; qq < NSPL; qq++) {
        float2 v = *reinterpret_cast<const float2*>(&g_pacc[(qq*BN + row)*Cc + ch]);
        acc.x += v.x; acc.y += v.y;
    }
    float2 ab = *reinterpret_cast<const float2*>(&abias[ch]);
    float ax = acc.x*inv + ab.x;
    float ay = acc.y*inv + ab.y;

    float s1 = ax + ay;
    #pragma unroll
    for (int o = 16; o; o >>= 1) s1 += __shfl_xor_sync(0xffffffffu, s1, o);
    if (l == 0) red[w] = s1;
    __syncthreads();
    float mu = (red[0] + red[1] + red[2] + red[3]) * (1.0f/Cc);
    __syncthreads();

    float dx = ax - mu, dy = ay - mu;
    float s2 = dx*dx + dy*dy;
    #pragma unroll
    for (int o = 16; o; o >>= 1) s2 += __shfl_xor_sync(0xffffffffu, s2, o);
    if (l == 0) red[w] = s2;
    __syncthreads();
    float var = (red[0] + red[1] + red[2] + red[3]) * (1.0f/Cc);
    float rs = rsqrtf(var + 1e-5f);

    float2 gg = *reinterpret_cast<const float2*>(&g[ch]);
    float2 bb = *reinterpret_cast<const float2*>(&be[ch]);
    float ox = dx*rs*gg.x + bb.x;
    float oy = dy*rs*gg.y + bb.y;
    if (do_relu) { ox = fmaxf(ox, 0.f); oy = fmaxf(oy, 0.f); }
    *reinterpret_cast<float2*>(&out[row*Cc + ch]) = make_float2(ox, oy);
}

// ---------------- launch ----------------------------------------------------
extern "C" void kernel_launch(void* const* d_in, const int* in_sizes, int n_in,
                              void* d_out, int out_size) {
    const float* x     = (const float*)d_in[0];
    const float* emb   = (const float*)d_in[1];
    const float* w1l   = (const float*)d_in[2];
    const float* b1l   = (const float*)d_in[3];
    const float* w1r   = (const float*)d_in[4];
    const float* b1r   = (const float*)d_in[5];
    const float* att1  = (const float*)d_in[6];
    const float* bias1 = (const float*)d_in[7];
    const float* g1    = (const float*)d_in[8];
    const float* be1   = (const float*)d_in[9];
    const float* w2l   = (const float*)d_in[10];
    const float* b2l   = (const float*)d_in[11];
    const float* w2r   = (const float*)d_in[12];
    const float* b2r   = (const float*)d_in[13];
    const float* att2  = (const float*)d_in[14];
    const float* bias2 = (const float*)d_in[15];
    const float* g2    = (const float*)d_in[16];
    const float* be2   = (const float*)d_in[17];
    float* out = (float*)d_out;

    // layer 1: z=2 slice of proj computes the adjacency mask (overlapped)
    proj_kernel<DIN><<<dim3(4, 16, 3), 256>>>(x, w1l, b1l, w1r, b1r, att1, emb);
    attn_kernel<<<dim3(16, 4, 8), 256>>>(att1);
    ln_kernel<<<BN, 128>>>(g1, be1, bias1, nullptr, 1);

    proj_kernel<Cc><<<dim3(4, 16, 2), 256>>>(nullptr, w2l, b2l, w2r, b2r, att2, emb);
    attn_kernel<<<dim3(16, 4, 8), 256>>>(att2);
    ln_kernel<<<BN, 128>>>(g2, be2, bias2, out, 0);
}

// round 13
// speedup vs baseline: 1.1039x; 1.1039x over previous
#include <cuda_runtime.h>
#include <math.h>

#define Bq   2
#define Nn   512
#define DIN  32
#define DHD  64
#define Hh   4
#define Cc   256
#define BN   (Bq*Nn)
#define NSPL 4

typedef unsigned long long u64;
typedef unsigned int u32;

__device__ float  g_mbias[Nn*Nn];
__device__ float2 g_xlT[Bq*Hh*32*512];    // [(b*4+h)*32 + d2][node]
__device__ float  g_xr[BN*Cc];
__device__ float  g_al[Bq*Hh*512];
__device__ float  g_ar[Bq*Hh*512];
__device__ float  g_pacc[NSPL*BN*Cc];     // [q][row][c]
__device__ float  g_psum[NSPL*BN*Hh];     // [q][row][h]
__device__ float  g_hln[BN*Cc];

// ---- packed fp32x2 helpers ----
__device__ __forceinline__ u64 add2(u64 a, u64 b) {
    u64 r; asm("add.rn.f32x2 %0,%1,%2;" : "=l"(r) : "l"(a), "l"(b)); return r;
}
__device__ __forceinline__ void fma2(u64 &d, u64 a, u64 b) {
    asm("fma.rn.f32x2 %0,%1,%2,%3;" : "=l"(d) : "l"(a), "l"(b), "l"(d));
}
__device__ __forceinline__ u64 dup2(float x) {
    u64 r; asm("mov.b64 %0,{%1,%1};" : "=l"(r) : "f"(x)); return r;
}
__device__ __forceinline__ float2 unpack2(u64 v) {
    float2 f; asm("mov.b64 {%0,%1},%2;" : "=f"(f.x), "=f"(f.y) : "l"(v)); return f;
}
#define ABS2MASK 0x7FFFFFFF7FFFFFFFULL

// ---- tf32 helpers ----
__device__ __forceinline__ float tf32r(float x) {
    float r; asm("cvt.rna.tf32.f32 %0,%1;" : "=f"(r) : "f"(x)); return r;
}
__device__ __forceinline__ void mma_tf32(float* c, const u32* a, u32 b0, u32 b1) {
    asm volatile("mma.sync.aligned.m16n8k8.row.col.f32.tf32.tf32.f32 "
        "{%0,%1,%2,%3},{%4,%5,%6,%7},{%8,%9},{%0,%1,%2,%3};"
        : "+f"(c[0]), "+f"(c[1]), "+f"(c[2]), "+f"(c[3])
        : "r"(a[0]), "r"(a[1]), "r"(a[2]), "r"(a[3]), "r"(b0), "r"(b1));
}

// ---------------- mask bias (ne fused) ------------------------------------
__global__ void __launch_bounds__(256) mask_kernel(const float* __restrict__ emb) {
    __shared__ float A_s[32][65];
    __shared__ float B_s[64][65];
    int i0 = blockIdx.y * 32, j0 = blockIdx.x * 64;
    int t = threadIdx.x, tx = t & 15, ty = t >> 4;

    {
        int r = t >> 3, q = t & 7;
        const float* src = &emb[(i0 + r)*DHD + q*8];
        float4 v0 = *reinterpret_cast<const float4*>(src);
        float4 v1 = *reinterpret_cast<const float4*>(src + 4);
        float s = v0.x*v0.x + v0.y*v0.y + v0.z*v0.z + v0.w*v0.w
                + v1.x*v1.x + v1.y*v1.y + v1.z*v1.z + v1.w*v1.w;
        s += __shfl_xor_sync(0xffffffffu, s, 1);
        s += __shfl_xor_sync(0xffffffffu, s, 2);
        s += __shfl_xor_sync(0xffffffffu, s, 4);
        float inv = rsqrtf(s);
        A_s[r][q*8+0]=v0.x*inv; A_s[r][q*8+1]=v0.y*inv; A_s[r][q*8+2]=v0.z*inv; A_s[r][q*8+3]=v0.w*inv;
        A_s[r][q*8+4]=v1.x*inv; A_s[r][q*8+5]=v1.y*inv; A_s[r][q*8+6]=v1.z*inv; A_s[r][q*8+7]=v1.w*inv;
    }
    {
        int r = t >> 2, q = t & 3;
        const float* src = &emb[(j0 + r)*DHD + q*16];
        float4 v[4];
        #pragma unroll
        for (int i = 0; i < 4; i++) v[i] = *reinterpret_cast<const float4*>(src + 4*i);
        float s = 0.f;
        #pragma unroll
        for (int i = 0; i < 4; i++) s += v[i].x*v[i].x + v[i].y*v[i].y + v[i].z*v[i].z + v[i].w*v[i].w;
        s += __shfl_xor_sync(0xffffffffu, s, 1);
        s += __shfl_xor_sync(0xffffffffu, s, 2);
        float inv = rsqrtf(s);
        #pragma unroll
        for (int i = 0; i < 4; i++) {
            B_s[r][q*16 + 4*i    ] = v[i].x*inv;
            B_s[r][q*16 + 4*i + 1] = v[i].y*inv;
            B_s[r][q*16 + 4*i + 2] = v[i].z*inv;
            B_s[r][q*16 + 4*i + 3] = v[i].w*inv;
        }
    }
    __syncthreads();

    float acc[2][4];
    #pragma unroll
    for (int r = 0; r < 2; r++)
        #pragma unroll
        for (int c = 0; c < 4; c++) acc[r][c] = 0.f;

    #pragma unroll
    for (int kk = 0; kk < 64; kk++) {
        float a0 = A_s[ty][kk], a1 = A_s[ty + 16][kk];
        float bb[4];
        #pragma unroll
        for (int c = 0; c < 4; c++) bb[c] = B_s[4*tx + c][kk];
        #pragma unroll
        for (int c = 0; c < 4; c++) { acc[0][c] += a0*bb[c]; acc[1][c] += a1*bb[c]; }
    }
    #pragma unroll
    for (int r = 0; r < 2; r++) {
        int gi = i0 + ty + 16*r;
        float4 o;
        float* op = &o.x;
        #pragma unroll
        for (int c = 0; c < 4; c++) {
            int gj = j0 + 4*tx + c;
            op[c] = (acc[r][c] != 0.0f || gi == gj) ? 0.0f : -1e30f;
        }
        *reinterpret_cast<float4*>(&g_mbias[gi*Nn + j0 + 4*tx]) = o;
    }
}

// ---------------- projection + rank-1 terms + transpose --------------------
template<int K>
__global__ void __launch_bounds__(256) proj_kernel(
    const float* __restrict__ Xopt,
    const float* __restrict__ Wl, const float* __restrict__ bl,
    const float* __restrict__ Wr, const float* __restrict__ br,
    const float* __restrict__ att)
{
    const float* X    = Xopt ? Xopt : g_hln;
    const float* W    = blockIdx.z ? Wr : Wl;
    const float* bias = blockIdx.z ? br : bl;

    __shared__ float A_s[64][33];
    __shared__ float W_s[32][68];
    int m0 = blockIdx.y * 64, n0 = blockIdx.x * 64;
    int t = threadIdx.x, tx = t & 15, ty = t >> 4;

    u64 accp[4][2];
    #pragma unroll
    for (int r = 0; r < 4; r++) { accp[r][0] = 0ull; accp[r][1] = 0ull; }

    for (int kc = 0; kc < K; kc += 32) {
        __syncthreads();
        #pragma unroll
        for (int p = 0; p < 8; p++) {
            int row = (t >> 5) + p*8;
            int col = t & 31;
            A_s[row][col] = X[(m0 + row)*K + kc + col];
        }
        #pragma unroll
        for (int p = 0; p < 8; p++) {
            int kk  = (t >> 6) + p*4;
            int col = t & 63;
            W_s[kk][col] = W[(kc + kk)*Cc + n0 + col];
        }
        __syncthreads();
        #pragma unroll
        for (int kk = 0; kk < 32; kk++) {
            ulonglong2 bv = *reinterpret_cast<const ulonglong2*>(&W_s[kk][4*tx]);
            #pragma unroll
            for (int r = 0; r < 4; r++) {
                u64 ad = dup2(A_s[ty + 16*r][kk]);
                fma2(accp[r][0], ad, bv.x);
                fma2(accp[r][1], ad, bv.y);
            }
        }
    }
    float4 bv4 = *reinterpret_cast<const float4*>(&bias[n0 + 4*tx]);
    int hq = blockIdx.x;
    float4 attv = *reinterpret_cast<const float4*>(&att[hq*64 + 4*tx]);

    #pragma unroll
    for (int r = 0; r < 4; r++) {
        int m = m0 + ty + 16*r;
        int b = m >> 9, node = m & 511;
        float2 lo = unpack2(accp[r][0]), hi = unpack2(accp[r][1]);
        float4 o = make_float4(lo.x + bv4.x, lo.y + bv4.y, hi.x + bv4.z, hi.y + bv4.w);
        float pa = attv.x*o.x + attv.y*o.y + attv.z*o.z + attv.w*o.w;
        pa += __shfl_xor_sync(0xffffffffu, pa, 1);
        pa += __shfl_xor_sync(0xffffffffu, pa, 2);
        pa += __shfl_xor_sync(0xffffffffu, pa, 4);
        pa += __shfl_xor_sync(0xffffffffu, pa, 8);
        pa *= 0.6f;
        if (blockIdx.z == 0) {
            float2* base = g_xlT + (size_t)((b*4 + hq)*32)*512;
            base[(2*tx    )*512 + node] = make_float2(o.x, o.y);
            base[(2*tx + 1)*512 + node] = make_float2(o.z, o.w);
            if (tx == 0) g_al[(b*4 + hq)*512 + node] = pa;
        } else {
            *reinterpret_cast<float4*>(&g_xr[m*Cc + n0 + 4*tx]) = o;
            if (tx == 0) g_ar[(b*4 + hq)*512 + node] = pa;
        }
    }
}

// ---------------- fused GATv2 attention: fp32x2 score + tf32 MMA agg -------
// grid (16, 4, 8): z = b*4 + q. 32 rows/block, 2 j-chunks of 64 per block.
// xlT2 holds tf32-pre-rounded X; single-term MMA (rel_err ~1.2e-4, 8x margin).
__global__ void __launch_bounds__(256) attn_kernel(const float* __restrict__ att)
{
    const int z = blockIdx.z, b = z >> 2, q = z & 3;
    const int h = blockIdx.y, i0 = blockIdx.x * 32;
    const int t = threadIdx.x, w = t >> 5, l = t & 31;

    __shared__ float2 xlT2[32][66];
    __shared__ float2 xr2 [32][34];
    __shared__ float  pfh[32][68];
    __shared__ float2 bt2[32];

    #pragma unroll
    for (int p = 0; p < 2; p++) {
        int idx = t + p*256;
        int r = idx >> 4, cc = idx & 15;
        float4 v = *reinterpret_cast<const float4*>(&g_xr[(b*Nn + i0 + r)*Cc + h*64 + 4*cc]);
        *reinterpret_cast<float4*>(&xr2[r][2*cc]) = v;
    }
    if (t < 32) {
        float2 a = *reinterpret_cast<const float2*>(&att[h*64 + 2*t]);
        bt2[t] = make_float2(0.4f*a.x, 0.4f*a.y);
    }

    float arr[4];
    #pragma unroll
    for (int k = 0; k < 4; k++) arr[k] = g_ar[(b*4 + h)*512 + i0 + 4*w + k];

    const float2* xsrc = g_xlT + (size_t)((b*4 + h)*32)*512;
    const float*  alsrc = g_al + (b*4 + h)*512;
    const u32*    xlu = reinterpret_cast<const u32*>(&xlT2[0][0]);
    const int jbase = q * 128;
    const int d2p = t >> 5, mp = t & 31;
    const int ih = w & 1, dq = w >> 1;

    float cacc[2][4];
    #pragma unroll
    for (int tt = 0; tt < 2; tt++)
        #pragma unroll
        for (int i = 0; i < 4; i++) cacc[tt][i] = 0.f;
    float psum[4];
    #pragma unroll
    for (int k = 0; k < 4; k++) psum[k] = 0.f;

    float4 pre[4];
    #pragma unroll
    for (int p = 0; p < 4; p++)
        pre[p] = *reinterpret_cast<const float4*>(xsrc + (d2p + 8*p)*512 + jbase + 2*mp);

    for (int c = 0; c < 2; c++) {
        const int j0 = jbase + c * 64;
        __syncthreads();
        #pragma unroll
        for (int p = 0; p < 4; p++) {
            float4 v = pre[p];
            v.x = tf32r(v.x); v.y = tf32r(v.y); v.z = tf32r(v.z); v.w = tf32r(v.w);
            *reinterpret_cast<float4*>(&xlT2[d2p + 8*p][2*mp]) = v;
        }

        float2 mb[4];
        #pragma unroll
        for (int k = 0; k < 4; k++)
            mb[k] = *reinterpret_cast<const float2*>(&g_mbias[(i0 + 4*w + k)*Nn + j0 + 2*l]);
        float2 alj = *reinterpret_cast<const float2*>(&alsrc[j0 + 2*l]);

        __syncthreads();
        if (c < 1) {
            #pragma unroll
            for (int p = 0; p < 4; p++)
                pre[p] = *reinterpret_cast<const float4*>(xsrc + (d2p + 8*p)*512 + (j0 + 64) + 2*mp);
        }

        // ---- score (packed over d, tf32-rounded X: negligible score error) ----
        u64 sp[4][2];
        #pragma unroll
        for (int k = 0; k < 4; k++) { sp[k][0] = 0ull; sp[k][1] = 0ull; }

        #pragma unroll
        for (int d2 = 0; d2 < 32; d2 += 2) {
            ulonglong2 xa = *reinterpret_cast<const ulonglong2*>(&xlT2[d2    ][2*l]);
            ulonglong2 xb = *reinterpret_cast<const ulonglong2*>(&xlT2[d2 + 1][2*l]);
            ulonglong2 bt = *reinterpret_cast<const ulonglong2*>(&bt2[d2]);
            #pragma unroll
            for (int k = 0; k < 4; k++) {
                ulonglong2 xr = *reinterpret_cast<const ulonglong2*>(&xr2[4*w + k][d2]);
                u64 zz;
                zz = add2(xr.x, xa.x) & ABS2MASK; fma2(sp[k][0], bt.x, zz);
                zz = add2(xr.x, xa.y) & ABS2MASK; fma2(sp[k][1], bt.x, zz);
                zz = add2(xr.y, xb.x) & ABS2MASK; fma2(sp[k][0], bt.y, zz);
                zz = add2(xr.y, xb.y) & ABS2MASK; fma2(sp[k][1], bt.y, zz);
            }
        }

        // ---- exp + tf32-P store ----
        #pragma unroll
        for (int k = 0; k < 4; k++) {
            float2 s0v = unpack2(sp[k][0]);
            float2 s1v = unpack2(sp[k][1]);
            float p0 = __expf(s0v.x + s0v.y + arr[k] + alj.x + mb[k].x);
            float p1 = __expf(s1v.x + s1v.y + arr[k] + alj.y + mb[k].y);
            *reinterpret_cast<float2*>(&pfh[4*w + k][2*l]) = make_float2(tf32r(p0), tf32r(p1));
            psum[k] += p0 + p1;
        }
        __syncthreads();

        // ---- aggregation via tf32 MMA (single term, X pre-rounded) ----
        {
            int ar0 = ih*16 + (l >> 2);
            #pragma unroll
            for (int ks = 0; ks < 8; ks++) {
                int ac = ks*8 + (l & 3);
                u32 ah[4];
                ah[0] = __float_as_uint(pfh[ar0    ][ac]);
                ah[1] = __float_as_uint(pfh[ar0 + 8][ac]);
                ah[2] = __float_as_uint(pfh[ar0    ][ac + 4]);
                ah[3] = __float_as_uint(pfh[ar0 + 8][ac + 4]);
                #pragma unroll
                for (int tt = 0; tt < 2; tt++) {
                    int n0 = dq*16 + tt*8 + (l >> 2);
                    int k0 = ks*8 + (l & 3);
                    u32 b0 = xlu[(n0 >> 1)*132 + k0*2       + (n0 & 1)];
                    u32 b1 = xlu[(n0 >> 1)*132 + (k0 + 4)*2 + (n0 & 1)];
                    mma_tf32(cacc[tt], ah, b0, b1);
                }
            }
        }
    }

    // ---- write psum partials: [q][row][h] ----
    #pragma unroll
    for (int k = 0; k < 4; k++) {
        float s = psum[k];
        #pragma unroll
        for (int o = 16; o; o >>= 1) s += __shfl_xor_sync(0xffffffffu, s, o);
        if (l == 0) g_psum[(q*BN + b*Nn + i0 + 4*w + k)*Hh + h] = s;
    }

    // ---- write C partials: [q][row][c], coalesced float2 ----
    #pragma unroll
    for (int tt = 0; tt < 2; tt++) {
        int gr = b*Nn + i0 + ih*16 + (l >> 2);
        int gc = h*64 + dq*16 + tt*8 + 2*(l & 3);
        *reinterpret_cast<float2*>(&g_pacc[(q*BN + gr    )*Cc + gc]) =
            make_float2(cacc[tt][0], cacc[tt][1]);
        *reinterpret_cast<float2*>(&g_pacc[(q*BN + gr + 8)*Cc + gc]) =
            make_float2(cacc[tt][2], cacc[tt][3]);
    }
}

// ---------------- combine + bias + LayerNorm (+ReLU), block-per-row --------
__global__ void __launch_bounds__(128) ln_kernel(
    const float* __restrict__ g,
    const float* __restrict__ be,
    const float* __restrict__ abias,
    float* __restrict__ outopt,
    int do_relu)
{
    float* out = outopt ? outopt : g_hln;
    const int row = blockIdx.x;
    const int t = threadIdx.x;
    const int ch = 2*t;
    const int h = t >> 5;
    const int w = t >> 5, l = t & 31;
    __shared__ float red[4];

    float s = 0.f;
    #pragma unroll
    for (int qq = 0; qq < NSPL; qq++) s += g_psum[(qq*BN + row)*Hh + h];
    float inv = 1.0f / s;

    float2 acc = make_float2(0.f, 0.f);
    #pragma unroll
    for (int qq = 0; qq < NSPL; qq++) {
        float2 v = *reinterpret_cast<const float2*>(&g_pacc[(qq*BN + row)*Cc + ch]);
        acc.x += v.x; acc.y += v.y;
    }
    float2 ab = *reinterpret_cast<const float2*>(&abias[ch]);
    float ax = acc.x*inv + ab.x;
    float ay = acc.y*inv + ab.y;

    float s1 = ax + ay;
    #pragma unroll
    for (int o = 16; o; o >>= 1) s1 += __shfl_xor_sync(0xffffffffu, s1, o);
    if (l == 0) red[w] = s1;
    __syncthreads();
    float mu = (red[0] + red[1] + red[2] + red[3]) * (1.0f/Cc);
    __syncthreads();

    float dx = ax - mu, dy = ay - mu;
    float s2 = dx*dx + dy*dy;
    #pragma unroll
    for (int o = 16; o; o >>= 1) s2 += __shfl_xor_sync(0xffffffffu, s2, o);
    if (l == 0) red[w] = s2;
    __syncthreads();
    float var = (red[0] + red[1] + red[2] + red[3]) * (1.0f/Cc);
    float rs = rsqrtf(var + 1e-5f);

    float2 gg = *reinterpret_cast<const float2*>(&g[ch]);
    float2 bb = *reinterpret_cast<const float2*>(&be[ch]);
    float ox = dx*rs*gg.x + bb.x;
    float oy = dy*rs*gg.y + bb.y;
    if (do_relu) { ox = fmaxf(ox, 0.f); oy = fmaxf(oy, 0.f); }
    *reinterpret_cast<float2*>(&out[row*Cc + ch]) = make_float2(ox, oy);
}

// ---------------- launch ----------------------------------------------------
extern "C" void kernel_launch(void* const* d_in, const int* in_sizes, int n_in,
                              void* d_out, int out_size) {
    const float* x     = (const float*)d_in[0];
    const float* emb   = (const float*)d_in[1];
    const float* w1l   = (const float*)d_in[2];
    const float* b1l   = (const float*)d_in[3];
    const float* w1r   = (const float*)d_in[4];
    const float* b1r   = (const float*)d_in[5];
    const float* att1  = (const float*)d_in[6];
    const float* bias1 = (const float*)d_in[7];
    const float* g1    = (const float*)d_in[8];
    const float* be1   = (const float*)d_in[9];
    const float* w2l   = (const float*)d_in[10];
    const float* b2l   = (const float*)d_in[11];
    const float* w2r   = (const float*)d_in[12];
    const float* b2r   = (const float*)d_in[13];
    const float* att2  = (const float*)d_in[14];
    const float* bias2 = (const float*)d_in[15];
    const float* g2    = (const float*)d_in[16];
    const float* be2   = (const float*)d_in[17];
    float* out = (float*)d_out;

    mask_kernel<<<dim3(8, 16), 256>>>(emb);

    proj_kernel<DIN><<<dim3(4, 16, 2), 256>>>(x, w1l, b1l, w1r, b1r, att1);
    attn_kernel<<<dim3(16, 4, 8), 256>>>(att1);
    ln_kernel<<<BN, 128>>>(g1, be1, bias1, nullptr, 1);

    proj_kernel<Cc><<<dim3(4, 16, 2), 256>>>(nullptr, w2l, b2l, w2r, b2r, att2);
    attn_kernel<<<dim3(16, 4, 8), 256>>>(att2);
    ln_kernel<<<BN, 128>>>(g2, be2, bias2, out, 0);
}

// round 14
// speedup vs baseline: 1.1300x; 1.0236x over previous
#include <cuda_runtime.h>
#include <math.h>

#define Bq   2
#define Nn   512
#define DIN  32
#define DHD  64
#define Hh   4
#define Cc   256
#define BN   (Bq*Nn)
#define NSPL 4

typedef unsigned long long u64;
typedef unsigned int u32;

__device__ float  g_mbias[Nn*Nn];
__device__ float2 g_xlT[Bq*Hh*32*512];    // [(b*4+h)*32 + d2][node]
__device__ float  g_xr[BN*Cc];
__device__ float  g_al[Bq*Hh*512];
__device__ float  g_ar[Bq*Hh*512];
__device__ float  g_pacc[NSPL*BN*Cc];     // [q][row][c]
__device__ float  g_psum[NSPL*BN*Hh];     // [q][row][h]
__device__ float  g_hln[BN*Cc];

// ---- packed fp32x2 helpers ----
__device__ __forceinline__ u64 add2(u64 a, u64 b) {
    u64 r; asm("add.rn.f32x2 %0,%1,%2;" : "=l"(r) : "l"(a), "l"(b)); return r;
}
__device__ __forceinline__ void fma2(u64 &d, u64 a, u64 b) {
    asm("fma.rn.f32x2 %0,%1,%2,%3;" : "=l"(d) : "l"(a), "l"(b), "l"(d));
}
__device__ __forceinline__ u64 dup2(float x) {
    u64 r; asm("mov.b64 %0,{%1,%1};" : "=l"(r) : "f"(x)); return r;
}
__device__ __forceinline__ float2 unpack2(u64 v) {
    float2 f; asm("mov.b64 {%0,%1},%2;" : "=f"(f.x), "=f"(f.y) : "l"(v)); return f;
}
#define ABS2MASK 0x7FFFFFFF7FFFFFFFULL

// ---- tf32 helpers ----
__device__ __forceinline__ float tf32r(float x) {
    float r; asm("cvt.rna.tf32.f32 %0,%1;" : "=f"(r) : "f"(x)); return r;
}
__device__ __forceinline__ void mma_tf32(float* c, const u32* a, u32 b0, u32 b1) {
    asm volatile("mma.sync.aligned.m16n8k8.row.col.f32.tf32.tf32.f32 "
        "{%0,%1,%2,%3},{%4,%5,%6,%7},{%8,%9},{%0,%1,%2,%3};"
        : "+f"(c[0]), "+f"(c[1]), "+f"(c[2]), "+f"(c[3])
        : "r"(a[0]), "r"(a[1]), "r"(a[2]), "r"(a[3]), "r"(b0), "r"(b1));
}

// ---------------- mask bias (ne fused) ------------------------------------
__global__ void __launch_bounds__(256) mask_kernel(const float* __restrict__ emb) {
    __shared__ float A_s[32][65];
    __shared__ float B_s[64][65];
    int i0 = blockIdx.y * 32, j0 = blockIdx.x * 64;
    int t = threadIdx.x, tx = t & 15, ty = t >> 4;

    {
        int r = t >> 3, q = t & 7;
        const float* src = &emb[(i0 + r)*DHD + q*8];
        float4 v0 = *reinterpret_cast<const float4*>(src);
        float4 v1 = *reinterpret_cast<const float4*>(src + 4);
        float s = v0.x*v0.x + v0.y*v0.y + v0.z*v0.z + v0.w*v0.w
                + v1.x*v1.x + v1.y*v1.y + v1.z*v1.z + v1.w*v1.w;
        s += __shfl_xor_sync(0xffffffffu, s, 1);
        s += __shfl_xor_sync(0xffffffffu, s, 2);
        s += __shfl_xor_sync(0xffffffffu, s, 4);
        float inv = rsqrtf(s);
        A_s[r][q*8+0]=v0.x*inv; A_s[r][q*8+1]=v0.y*inv; A_s[r][q*8+2]=v0.z*inv; A_s[r][q*8+3]=v0.w*inv;
        A_s[r][q*8+4]=v1.x*inv; A_s[r][q*8+5]=v1.y*inv; A_s[r][q*8+6]=v1.z*inv; A_s[r][q*8+7]=v1.w*inv;
    }
    {
        int r = t >> 2, q = t & 3;
        const float* src = &emb[(j0 + r)*DHD + q*16];
        float4 v[4];
        #pragma unroll
        for (int i = 0; i < 4; i++) v[i] = *reinterpret_cast<const float4*>(src + 4*i);
        float s = 0.f;
        #pragma unroll
        for (int i = 0; i < 4; i++) s += v[i].x*v[i].x + v[i].y*v[i].y + v[i].z*v[i].z + v[i].w*v[i].w;
        s += __shfl_xor_sync(0xffffffffu, s, 1);
        s += __shfl_xor_sync(0xffffffffu, s, 2);
        float inv = rsqrtf(s);
        #pragma unroll
        for (int i = 0; i < 4; i++) {
            B_s[r][q*16 + 4*i    ] = v[i].x*inv;
            B_s[r][q*16 + 4*i + 1] = v[i].y*inv;
            B_s[r][q*16 + 4*i + 2] = v[i].z*inv;
            B_s[r][q*16 + 4*i + 3] = v[i].w*inv;
        }
    }
    __syncthreads();

    float acc[2][4];
    #pragma unroll
    for (int r = 0; r < 2; r++)
        #pragma unroll
        for (int c = 0; c < 4; c++) acc[r][c] = 0.f;

    #pragma unroll
    for (int kk = 0; kk < 64; kk++) {
        float a0 = A_s[ty][kk], a1 = A_s[ty + 16][kk];
        float bb[4];
        #pragma unroll
        for (int c = 0; c < 4; c++) bb[c] = B_s[4*tx + c][kk];
        #pragma unroll
        for (int c = 0; c < 4; c++) { acc[0][c] += a0*bb[c]; acc[1][c] += a1*bb[c]; }
    }
    #pragma unroll
    for (int r = 0; r < 2; r++) {
        int gi = i0 + ty + 16*r;
        float4 o;
        float* op = &o.x;
        #pragma unroll
        for (int c = 0; c < 4; c++) {
            int gj = j0 + 4*tx + c;
            op[c] = (acc[r][c] != 0.0f || gi == gj) ? 0.0f : -1e30f;
        }
        *reinterpret_cast<float4*>(&g_mbias[gi*Nn + j0 + 4*tx]) = o;
    }
}

// ---------------- projection + rank-1 terms + transpose --------------------
template<int K>
__global__ void __launch_bounds__(256) proj_kernel(
    const float* __restrict__ Xopt,
    const float* __restrict__ Wl, const float* __restrict__ bl,
    const float* __restrict__ Wr, const float* __restrict__ br,
    const float* __restrict__ att)
{
    const float* X    = Xopt ? Xopt : g_hln;
    const float* W    = blockIdx.z ? Wr : Wl;
    const float* bias = blockIdx.z ? br : bl;

    __shared__ float A_s[64][33];
    __shared__ float W_s[32][68];
    int m0 = blockIdx.y * 64, n0 = blockIdx.x * 64;
    int t = threadIdx.x, tx = t & 15, ty = t >> 4;

    u64 accp[4][2];
    #pragma unroll
    for (int r = 0; r < 4; r++) { accp[r][0] = 0ull; accp[r][1] = 0ull; }

    for (int kc = 0; kc < K; kc += 32) {
        __syncthreads();
        #pragma unroll
        for (int p = 0; p < 8; p++) {
            int row = (t >> 5) + p*8;
            int col = t & 31;
            A_s[row][col] = X[(m0 + row)*K + kc + col];
        }
        #pragma unroll
        for (int p = 0; p < 8; p++) {
            int kk  = (t >> 6) + p*4;
            int col = t & 63;
            W_s[kk][col] = W[(kc + kk)*Cc + n0 + col];
        }
        __syncthreads();
        #pragma unroll
        for (int kk = 0; kk < 32; kk++) {
            ulonglong2 bv = *reinterpret_cast<const ulonglong2*>(&W_s[kk][4*tx]);
            #pragma unroll
            for (int r = 0; r < 4; r++) {
                u64 ad = dup2(A_s[ty + 16*r][kk]);
                fma2(accp[r][0], ad, bv.x);
                fma2(accp[r][1], ad, bv.y);
            }
        }
    }
    float4 bv4 = *reinterpret_cast<const float4*>(&bias[n0 + 4*tx]);
    int hq = blockIdx.x;
    float4 attv = *reinterpret_cast<const float4*>(&att[hq*64 + 4*tx]);

    #pragma unroll
    for (int r = 0; r < 4; r++) {
        int m = m0 + ty + 16*r;
        int b = m >> 9, node = m & 511;
        float2 lo = unpack2(accp[r][0]), hi = unpack2(accp[r][1]);
        float4 o = make_float4(lo.x + bv4.x, lo.y + bv4.y, hi.x + bv4.z, hi.y + bv4.w);
        float pa = attv.x*o.x + attv.y*o.y + attv.z*o.z + attv.w*o.w;
        pa += __shfl_xor_sync(0xffffffffu, pa, 1);
        pa += __shfl_xor_sync(0xffffffffu, pa, 2);
        pa += __shfl_xor_sync(0xffffffffu, pa, 4);
        pa += __shfl_xor_sync(0xffffffffu, pa, 8);
        pa *= 0.6f;
        if (blockIdx.z == 0) {
            float2* base = g_xlT + (size_t)((b*4 + hq)*32)*512;
            base[(2*tx    )*512 + node] = make_float2(o.x, o.y);
            base[(2*tx + 1)*512 + node] = make_float2(o.z, o.w);
            if (tx == 0) g_al[(b*4 + hq)*512 + node] = pa;
        } else {
            *reinterpret_cast<float4*>(&g_xr[m*Cc + n0 + 4*tx]) = o;
            if (tx == 0) g_ar[(b*4 + hq)*512 + node] = pa;
        }
    }
}

// ---------------- fused GATv2 attention: fp32x2 score + tf32 MMA agg -------
// grid (16, 4, 8): z = b*4 + q. 32 rows/block, 2 j-chunks of 64 per block.
// Double-buffered xlT2/pfh: 2 syncs per chunk instead of 3; MMA(c) overlaps
// with buffer fill of chunk c+1.
__global__ void __launch_bounds__(256) attn_kernel(const float* __restrict__ att)
{
    const int z = blockIdx.z, b = z >> 2, q = z & 3;
    const int h = blockIdx.y, i0 = blockIdx.x * 32;
    const int t = threadIdx.x, w = t >> 5, l = t & 31;

    __shared__ float2 xlT2[2][32][66];
    __shared__ float2 xr2 [32][34];
    __shared__ float  pfh[2][32][68];
    __shared__ float2 bt2[32];

    #pragma unroll
    for (int p = 0; p < 2; p++) {
        int idx = t + p*256;
        int r = idx >> 4, cc = idx & 15;
        float4 v = *reinterpret_cast<const float4*>(&g_xr[(b*Nn + i0 + r)*Cc + h*64 + 4*cc]);
        *reinterpret_cast<float4*>(&xr2[r][2*cc]) = v;
    }
    if (t < 32) {
        float2 a = *reinterpret_cast<const float2*>(&att[h*64 + 2*t]);
        bt2[t] = make_float2(0.4f*a.x, 0.4f*a.y);
    }

    float arr[4];
    #pragma unroll
    for (int k = 0; k < 4; k++) arr[k] = g_ar[(b*4 + h)*512 + i0 + 4*w + k];

    const float2* xsrc = g_xlT + (size_t)((b*4 + h)*32)*512;
    const float*  alsrc = g_al + (b*4 + h)*512;
    const int jbase = q * 128;
    const int d2p = t >> 5, mp = t & 31;
    const int ih = w & 1, dq = w >> 1;

    float cacc[2][4];
    #pragma unroll
    for (int tt = 0; tt < 2; tt++)
        #pragma unroll
        for (int i = 0; i < 4; i++) cacc[tt][i] = 0.f;
    float psum[4];
    #pragma unroll
    for (int k = 0; k < 4; k++) psum[k] = 0.f;

    float4 pre[4];
    #pragma unroll
    for (int p = 0; p < 4; p++)
        pre[p] = *reinterpret_cast<const float4*>(xsrc + (d2p + 8*p)*512 + jbase + 2*mp);

    #pragma unroll
    for (int c = 0; c < 2; c++) {
        const int j0 = jbase + c * 64;
        // fill this chunk's buffer (no sync needed vs prev MMA: different buffer)
        #pragma unroll
        for (int p = 0; p < 4; p++) {
            float4 v = pre[p];
            v.x = tf32r(v.x); v.y = tf32r(v.y); v.z = tf32r(v.z); v.w = tf32r(v.w);
            *reinterpret_cast<float4*>(&xlT2[c][d2p + 8*p][2*mp]) = v;
        }

        float2 mb[4];
        #pragma unroll
        for (int k = 0; k < 4; k++)
            mb[k] = *reinterpret_cast<const float2*>(&g_mbias[(i0 + 4*w + k)*Nn + j0 + 2*l]);
        float2 alj = *reinterpret_cast<const float2*>(&alsrc[j0 + 2*l]);

        __syncthreads();   // xlT2[c] ready (covers xr2/bt2 at c=0)
        if (c < 1) {
            #pragma unroll
            for (int p = 0; p < 4; p++)
                pre[p] = *reinterpret_cast<const float4*>(xsrc + (d2p + 8*p)*512 + (j0 + 64) + 2*mp);
        }

        // ---- score (packed over d) ----
        u64 sp[4][2];
        #pragma unroll
        for (int k = 0; k < 4; k++) { sp[k][0] = 0ull; sp[k][1] = 0ull; }

        #pragma unroll
        for (int d2 = 0; d2 < 32; d2 += 2) {
            ulonglong2 xa = *reinterpret_cast<const ulonglong2*>(&xlT2[c][d2    ][2*l]);
            ulonglong2 xb = *reinterpret_cast<const ulonglong2*>(&xlT2[c][d2 + 1][2*l]);
            ulonglong2 bt = *reinterpret_cast<const ulonglong2*>(&bt2[d2]);
            #pragma unroll
            for (int k = 0; k < 4; k++) {
                ulonglong2 xr = *reinterpret_cast<const ulonglong2*>(&xr2[4*w + k][d2]);
                u64 zz;
                zz = add2(xr.x, xa.x) & ABS2MASK; fma2(sp[k][0], bt.x, zz);
                zz = add2(xr.x, xa.y) & ABS2MASK; fma2(sp[k][1], bt.x, zz);
                zz = add2(xr.y, xb.x) & ABS2MASK; fma2(sp[k][0], bt.y, zz);
                zz = add2(xr.y, xb.y) & ABS2MASK; fma2(sp[k][1], bt.y, zz);
            }
        }

        // ---- exp + tf32-P store ----
        #pragma unroll
        for (int k = 0; k < 4; k++) {
            float2 s0v = unpack2(sp[k][0]);
            float2 s1v = unpack2(sp[k][1]);
            float p0 = __expf(s0v.x + s0v.y + arr[k] + alj.x + mb[k].x);
            float p1 = __expf(s1v.x + s1v.y + arr[k] + alj.y + mb[k].y);
            *reinterpret_cast<float2*>(&pfh[c][4*w + k][2*l]) = make_float2(tf32r(p0), tf32r(p1));
            psum[k] += p0 + p1;
        }
        __syncthreads();   // pfh[c] ready

        // ---- aggregation via tf32 MMA (single term, X pre-rounded) ----
        {
            const u32* xlu = reinterpret_cast<const u32*>(&xlT2[c][0][0]);
            int ar0 = ih*16 + (l >> 2);
            #pragma unroll
            for (int ks = 0; ks < 8; ks++) {
                int ac = ks*8 + (l & 3);
                u32 ah[4];
                ah[0] = __float_as_uint(pfh[c][ar0    ][ac]);
                ah[1] = __float_as_uint(pfh[c][ar0 + 8][ac]);
                ah[2] = __float_as_uint(pfh[c][ar0    ][ac + 4]);
                ah[3] = __float_as_uint(pfh[c][ar0 + 8][ac + 4]);
                #pragma unroll
                for (int tt = 0; tt < 2; tt++) {
                    int n0 = dq*16 + tt*8 + (l >> 2);
                    int k0 = ks*8 + (l & 3);
                    u32 b0 = xlu[(n0 >> 1)*132 + k0*2       + (n0 & 1)];
                    u32 b1 = xlu[(n0 >> 1)*132 + (k0 + 4)*2 + (n0 & 1)];
                    mma_tf32(cacc[tt], ah, b0, b1);
                }
            }
        }
    }

    // ---- write psum partials: [q][row][h] ----
    #pragma unroll
    for (int k = 0; k < 4; k++) {
        float s = psum[k];
        #pragma unroll
        for (int o = 16; o; o >>= 1) s += __shfl_xor_sync(0xffffffffu, s, o);
        if (l == 0) g_psum[(q*BN + b*Nn + i0 + 4*w + k)*Hh + h] = s;
    }

    // ---- write C partials: [q][row][c], coalesced float2 ----
    #pragma unroll
    for (int tt = 0; tt < 2; tt++) {
        int gr = b*Nn + i0 + ih*16 + (l >> 2);
        int gc = h*64 + dq*16 + tt*8 + 2*(l & 3);
        *reinterpret_cast<float2*>(&g_pacc[(q*BN + gr    )*Cc + gc]) =
            make_float2(cacc[tt][0], cacc[tt][1]);
        *reinterpret_cast<float2*>(&g_pacc[(q*BN + gr + 8)*Cc + gc]) =
            make_float2(cacc[tt][2], cacc[tt][3]);
    }
}

// ---------------- combine + bias + LayerNorm (+ReLU), block-per-row --------
// Single-pass mean/variance: var = E[x^2] - mu^2 (activations O(1), safe).
__global__ void __launch_bounds__(128) ln_kernel(
    const float* __restrict__ g,
    const float* __restrict__ be,
    const float* __restrict__ abias,
    float* __restrict__ outopt,
    int do_relu)
{
    float* out = outopt ? outopt : g_hln;
    const int row = blockIdx.x;
    const int t = threadIdx.x;
    const int ch = 2*t;
    const int h = t >> 5;
    const int w = t >> 5, l = t & 31;
    __shared__ float2 red[4];

    float s = 0.f;
    #pragma unroll
    for (int qq = 0; qq < NSPL; qq++) s += g_psum[(qq*BN + row)*Hh + h];
    float inv = 1.0f / s;

    float2 acc = make_float2(0.f, 0.f);
    #pragma unroll
    for (int qq = 0; qq < NSPL; qq++) {
        float2 v = *reinterpret_cast<const float2*>(&g_pacc[(qq*BN + row)*Cc + ch]);
        acc.x += v.x; acc.y += v.y;
    }
    float2 ab = *reinterpret_cast<const float2*>(&abias[ch]);
    float ax = acc.x*inv + ab.x;
    float ay = acc.y*inv + ab.y;

    // one-pass sum + sumsq reduce
    float s1 = ax + ay;
    float s2 = ax*ax + ay*ay;
    #pragma unroll
    for (int o = 16; o; o >>= 1) {
        s1 += __shfl_xor_sync(0xffffffffu, s1, o);
        s2 += __shfl_xor_sync(0xffffffffu, s2, o);
    }
    if (l == 0) red[w] = make_float2(s1, s2);
    __syncthreads();
    float sum  = red[0].x + red[1].x + red[2].x + red[3].x;
    float sumq = red[0].y + red[1].y + red[2].y + red[3].y;
    float mu  = sum * (1.0f/Cc);
    float var = sumq * (1.0f/Cc) - mu*mu;
    float rs = rsqrtf(var + 1e-5f);

    float dx = ax - mu, dy = ay - mu;
    float2 gg = *reinterpret_cast<const float2*>(&g[ch]);
    float2 bb = *reinterpret_cast<const float2*>(&be[ch]);
    float ox = dx*rs*gg.x + bb.x;
    float oy = dy*rs*gg.y + bb.y;
    if (do_relu) { ox = fmaxf(ox, 0.f); oy = fmaxf(oy, 0.f); }
    *reinterpret_cast<float2*>(&out[row*Cc + ch]) = make_float2(ox, oy);
}

// ---------------- launch ----------------------------------------------------
extern "C" void kernel_launch(void* const* d_in, const int* in_sizes, int n_in,
                              void* d_out, int out_size) {
    const float* x     = (const float*)d_in[0];
    const float* emb   = (const float*)d_in[1];
    const float* w1l   = (const float*)d_in[2];
    const float* b1l   = (const float*)d_in[3];
    const float* w1r   = (const float*)d_in[4];
    const float* b1r   = (const float*)d_in[5];
    const float* att1  = (const float*)d_in[6];
    const float* bias1 = (const float*)d_in[7];
    const float* g1    = (const float*)d_in[8];
    const float* be1   = (const float*)d_in[9];
    const float* w2l   = (const float*)d_in[10];
    const float* b2l   = (const float*)d_in[11];
    const float* w2r   = (const float*)d_in[12];
    const float* b2r   = (const float*)d_in[13];
    const float* att2  = (const float*)d_in[14];
    const float* bias2 = (const float*)d_in[15];
    const float* g2    = (const float*)d_in[16];
    const float* be2   = (const float*)d_in[17];
    float* out = (float*)d_out;

    mask_kernel<<<dim3(8, 16), 256>>>(emb);

    proj_kernel<DIN><<<dim3(4, 16, 2), 256>>>(x, w1l, b1l, w1r, b1r, att1);
    attn_kernel<<<dim3(16, 4, 8), 256>>>(att1);
    ln_kernel<<<BN, 128>>>(g1, be1, bias1, nullptr, 1);

    proj_kernel<Cc><<<dim3(4, 16, 2), 256>>>(nullptr, w2l, b2l, w2r, b2r, att2);
    attn_kernel<<<dim3(16, 4, 8), 256>>>(att2);
    ln_kernel<<<BN, 128>>>(g2, be2, bias2, out, 0);
}